// round 9
// baseline (speedup 1.0000x reference)
#include <cuda_runtime.h>
#include <cuda_bf16.h>
#include <cstdint>
#include <math_constants.h>

#define Bq 8
#define Nq 2048
#define Dq 128
#define ALPHA 0.2f

// ---------------- scratch (device globals; no allocations allowed) ----------
__device__ float g_w1[Dq];
__device__ float g_w2[Dq];
__device__ float g_Wh1[Bq * Nq];
__device__ float g_Wh2[Bq * Nq];
__device__ __nv_bfloat16 g_Whb[(size_t)Bq * Nq * Dq];   // 4 MB bf16 Wh

// ---------------- K0: w1 = W @ a[:d], w2 = W @ a[d:] ------------------------
__global__ void k_wa(const float* __restrict__ W, const float* __restrict__ a) {
    int k = threadIdx.x;                 // 128 threads
    float s1 = 0.f, s2 = 0.f;
    #pragma unroll 8
    for (int j = 0; j < Dq; j++) {
        float w = W[k * Dq + j];
        s1 += w * a[j];
        s2 += w * a[Dq + j];
    }
    g_w1[k] = s1;
    g_w2[k] = s2;
}

// ---------------- K1: Wh1[row] = h[row]·w1, Wh2[row] = h[row]·w2 ------------
__global__ void __launch_bounds__(256) k_wh12(const float* __restrict__ h) {
    int row  = blockIdx.x * 8 + (threadIdx.x >> 5);
    int lane = threadIdx.x & 31;
    float4 v  = *(const float4*)&h[(size_t)row * Dq + lane * 4];
    float4 u1 = *(const float4*)&g_w1[lane * 4];
    float4 u2 = *(const float4*)&g_w2[lane * 4];
    float s1 = v.x * u1.x + v.y * u1.y + v.z * u1.z + v.w * u1.w;
    float s2 = v.x * u2.x + v.y * u2.y + v.z * u2.z + v.w * u2.w;
    #pragma unroll
    for (int o = 16; o; o >>= 1) {
        s1 += __shfl_xor_sync(0xffffffffu, s1, o);
        s2 += __shfl_xor_sync(0xffffffffu, s2, o);
    }
    if (lane == 0) { g_Wh1[row] = s1; g_Wh2[row] = s2; }
}

// ---------------- K2: Wh = h @ W (fp32 compute) -> bf16 scratch -------------
#define TM2 128
__global__ void __launch_bounds__(256) k_wh(const float* __restrict__ h,
                                            const float* __restrict__ W) {
    __shared__ float As[32][TM2 + 4];   // [k][m] transposed h chunk
    __shared__ float Bs[32][Dq + 4];    // [k][c] W chunk
    const int m0  = blockIdx.x * TM2;
    const int tid = threadIdx.x;
    const int tx  = tid & 15, ty = tid >> 4;

    float acc[8][8];
    #pragma unroll
    for (int i = 0; i < 8; i++)
        #pragma unroll
        for (int j = 0; j < 8; j++) acc[i][j] = 0.f;

    for (int kc = 0; kc < Dq; kc += 32) {
        for (int i = tid; i < 128 * 8; i += 256) {
            int m = i >> 3, f = i & 7;
            float4 v = *(const float4*)&h[(size_t)(m0 + m) * Dq + kc + f * 4];
            As[f * 4 + 0][m] = v.x;
            As[f * 4 + 1][m] = v.y;
            As[f * 4 + 2][m] = v.z;
            As[f * 4 + 3][m] = v.w;
        }
        for (int i = tid; i < 32 * 32; i += 256) {
            int k = i >> 5, f = i & 31;
            *(float4*)&Bs[k][f * 4] = *(const float4*)&W[(size_t)(kc + k) * Dq + f * 4];
        }
        __syncthreads();
        #pragma unroll 8
        for (int k = 0; k < 32; k++) {
            float a8[8], b8[8];
            *(float4*)&a8[0] = *(const float4*)&As[k][ty * 8];
            *(float4*)&a8[4] = *(const float4*)&As[k][ty * 8 + 4];
            *(float4*)&b8[0] = *(const float4*)&Bs[k][tx * 8];
            *(float4*)&b8[4] = *(const float4*)&Bs[k][tx * 8 + 4];
            #pragma unroll
            for (int i = 0; i < 8; i++)
                #pragma unroll
                for (int j = 0; j < 8; j++)
                    acc[i][j] += a8[i] * b8[j];
        }
        __syncthreads();
    }
    #pragma unroll
    for (int i = 0; i < 8; i++) {
        int row = m0 + ty * 8 + i;
        __nv_bfloat162* dst = (__nv_bfloat162*)(g_Whb + (size_t)row * Dq + tx * 8);
        #pragma unroll
        for (int j = 0; j < 4; j++) {
            __nv_bfloat162 t;
            t.x = __float2bfloat16_rn(acc[i][2 * j]);
            t.y = __float2bfloat16_rn(acc[i][2 * j + 1]);
            dst[j] = t;
        }
    }
}

// ---------------- K3 (fused): softmax + attention write + attn @ Wh ---------
// One block = 64 rows of one batch. 256 threads (8 warps).
// Pass A: stream adj once, pack mask bits to smem, online softmax (m, s).
// Pass C: per 128-col K-tile: recompute p, write attention (fp32 out),
//         stage p as bf16 + Wh tile to smem, mma.sync accumulate.
__device__ __forceinline__ void ldmA4(uint32_t* a, uint32_t addr) {
    asm volatile("ldmatrix.sync.aligned.m8n8.x4.shared.b16 {%0,%1,%2,%3}, [%4];"
                 : "=r"(a[0]), "=r"(a[1]), "=r"(a[2]), "=r"(a[3]) : "r"(addr));
}
__device__ __forceinline__ void ldmBt2(uint32_t* b, uint32_t addr) {
    asm volatile("ldmatrix.sync.aligned.m8n8.x2.trans.shared.b16 {%0,%1}, [%2];"
                 : "=r"(b[0]), "=r"(b[1]) : "r"(addr));
}
__device__ __forceinline__ void mma16816(float* c, const uint32_t* a, const uint32_t* b) {
    asm volatile("mma.sync.aligned.m16n8k16.row.col.f32.bf16.bf16.f32 "
                 "{%0,%1,%2,%3}, {%4,%5,%6,%7}, {%8,%9}, {%0,%1,%2,%3};"
                 : "+f"(c[0]), "+f"(c[1]), "+f"(c[2]), "+f"(c[3])
                 : "r"(a[0]), "r"(a[1]), "r"(a[2]), "r"(a[3]), "r"(b[0]), "r"(b[1]));
}

#define ROWS_F 64
#define KTILE 128
#define STR 136                       // bf16 row stride (pad 8)
#define SM_WH2  0                     // 2048 f32          = 8192 B
#define SM_MSK  8192                  // 64*64 u32         = 16384 B
#define SM_AS   24576                 // 64*136 bf16       = 17408 B
#define SM_BS   41984                 // 128*136 bf16      = 34816 B
#define SM_TOT  76800

__global__ void __launch_bounds__(256, 2) k_fused(const int* __restrict__ adj,
                                                  const float* __restrict__ h,
                                                  float* __restrict__ out,
                                                  float* __restrict__ attn) {
    extern __shared__ char sm[];
    float*         wh2s = (float*)(sm + SM_WH2);
    uint32_t*      msk  = (uint32_t*)(sm + SM_MSK);
    __nv_bfloat16* As   = (__nv_bfloat16*)(sm + SM_AS);
    __nv_bfloat16* Bs   = (__nv_bfloat16*)(sm + SM_BS);

    const int tid  = threadIdx.x;
    const int lane = tid & 31;
    const int wid  = tid >> 5;
    const int wy   = wid >> 2;            // 0..1  (32-row strip)
    const int wx   = wid & 3;             // 0..3  (32-col strip)
    const int b    = blockIdx.x >> 5;     // batch
    const int rb0  = (blockIdx.x & 31) * ROWS_F;

    // ---- stage Wh2 (2048 floats) ----
    {
        const float* wh2g = g_Wh2 + (size_t)b * Nq;
        int i = tid * 8;
        *(float4*)&wh2s[i]     = *(const float4*)&wh2g[i];
        *(float4*)&wh2s[i + 4] = *(const float4*)&wh2g[i + 4];
    }
    __syncthreads();

    // ---- pass A: adj stream -> mask bits + online softmax (m, s) ----
    const int r  = tid >> 2;              // 0..63 row within tile
    const int q  = tid & 3;               // quad: col chunk of 512
    const int gr = b * Nq + rb0 + r;      // global row
    const int*   arow = adj + (size_t)gr * Nq;
    const float  wh1r = g_Wh1[gr];

    float m = -CUDART_INF_F, s = 0.f;
    const int c0 = q * 512;
    #pragma unroll 1
    for (int cw = 0; cw < 16; cw++) {
        uint32_t wbits = 0;
        const int cbase = c0 + cw * 32;
        #pragma unroll
        for (int jj = 0; jj < 32; jj += 4) {
            int4   av = *(const int4*)&arow[cbase + jj];
            float4 v  = *(const float4*)&wh2s[cbase + jj];
            float xs[4] = {v.x, v.y, v.z, v.w};
            int   aa[4] = {av.x, av.y, av.z, av.w};
            #pragma unroll
            for (int u = 0; u < 4; u++) {
                float x = wh1r + xs[u];
                float e = x > 0.f ? x : ALPHA * x;
                if (aa[u] > 0) {
                    wbits |= 1u << (jj + u);
                    if (e <= m) s += __expf(e - m);
                    else { s = s * __expf(m - e) + 1.f; m = e; }
                }
            }
        }
        msk[r * 64 + (cbase >> 5)] = wbits;
    }
    // combine the 4 quad-threads of this row (same warp)
    #pragma unroll
    for (int off = 1; off < 4; off <<= 1) {
        float mo = __shfl_xor_sync(0xffffffffu, m, off);
        float so = __shfl_xor_sync(0xffffffffu, s, off);
        float mn = fmaxf(m, mo);
        s = s * __expf(m - mn) + so * __expf(mo - mn);
        m = mn;
    }
    const float inv = 1.0f / s;
    __syncthreads();

    // ---- pass C: K-tiles of 128 cols ----
    float acc[2][4][4];
    #pragma unroll
    for (int t = 0; t < 2; t++)
        #pragma unroll
        for (int u = 0; u < 4; u++)
            #pragma unroll
            for (int p2 = 0; p2 < 4; p2++) acc[t][u][p2] = 0.f;

    const uint32_t as0 = (uint32_t)__cvta_generic_to_shared(As);
    const uint32_t bs0 = (uint32_t)__cvta_generic_to_shared(Bs);
    const int cp = q * 32;                                 // tile-local col base
    const __nv_bfloat16* whb = g_Whb + (size_t)b * Nq * Dq;
    float* arow_out = attn + (size_t)gr * Nq;

    const int brF = tid >> 1;            // B-stage: row 0..127
    const int bcF = (tid & 1) * 64;      // col 0 / 64

    #pragma unroll 1
    for (int kt = 0; kt < Nq / KTILE; kt++) {
        const int ck = kt * KTILE;
        // p subtile: compute, write attention, stage bf16 to As
        {
            const uint32_t wbits = msk[r * 64 + ((ck + cp) >> 5)];
            #pragma unroll
            for (int j = 0; j < 32; j += 4) {
                float4 v = *(const float4*)&wh2s[ck + cp + j];
                float pv[4];
                float xs[4] = {v.x, v.y, v.z, v.w};
                #pragma unroll
                for (int u = 0; u < 4; u++) {
                    float x = wh1r + xs[u];
                    float e = x > 0.f ? x : ALPHA * x;
                    pv[u] = ((wbits >> (j + u)) & 1u) ? __expf(e - m) * inv : 0.f;
                }
                *(float4*)&arow_out[ck + cp + j] = *(float4*)pv;
                __nv_bfloat162 lo, hi;
                lo.x = __float2bfloat16_rn(pv[0]); lo.y = __float2bfloat16_rn(pv[1]);
                hi.x = __float2bfloat16_rn(pv[2]); hi.y = __float2bfloat16_rn(pv[3]);
                uint2 pk;
                pk.x = *(uint32_t*)&lo; pk.y = *(uint32_t*)&hi;
                *(uint2*)&As[r * STR + cp + j] = pk;
            }
        }
        // stage Wh tile 128x128 bf16
        {
            const __nv_bfloat16* wb = whb + (size_t)(ck + brF) * Dq + bcF;
            #pragma unroll
            for (int ii = 0; ii < 8; ii++) {
                uint4 tv = *(const uint4*)(wb + ii * 8);
                *(uint4*)&Bs[brF * STR + bcF + ii * 8] = tv;
            }
        }
        __syncthreads();
        // mma: 8 k-steps of 16
        #pragma unroll
        for (int kk = 0; kk < KTILE; kk += 16) {
            uint32_t afr[2][4];
            #pragma unroll
            for (int t = 0; t < 2; t++) {
                int mr = wy * 32 + t * 16 + (lane & 15);
                uint32_t addr = as0 + ((uint32_t)mr * STR + kk + ((lane >> 4) << 3)) * 2u;
                ldmA4(afr[t], addr);
            }
            uint32_t bfr[4][2];
            #pragma unroll
            for (int u = 0; u < 4; u++) {
                int k = kk + (lane & 15);
                int n = wx * 32 + u * 8;
                uint32_t addr = bs0 + ((uint32_t)k * STR + n) * 2u;
                ldmBt2(bfr[u], addr);
            }
            #pragma unroll
            for (int t = 0; t < 2; t++)
                #pragma unroll
                for (int u = 0; u < 4; u++)
                    mma16816(acc[t][u], afr[t], bfr[u]);
        }
        __syncthreads();
    }

    // ---- epilogue: out = h + acc ----
    #pragma unroll
    for (int t = 0; t < 2; t++) {
        #pragma unroll
        for (int u = 0; u < 4; u++) {
            int rr = rb0 + wy * 32 + t * 16 + (lane >> 2);
            int cc = wx * 32 + u * 8 + (lane & 3) * 2;
            size_t base = ((size_t)b * Nq + rr) * Dq + cc;
            float2 hv = *(const float2*)&h[base];
            float2 ov;
            ov.x = hv.x + acc[t][u][0];
            ov.y = hv.y + acc[t][u][1];
            *(float2*)&out[base] = ov;
            size_t base2 = base + (size_t)8 * Dq;
            float2 hv2 = *(const float2*)&h[base2];
            float2 ov2;
            ov2.x = hv2.x + acc[t][u][2];
            ov2.y = hv2.y + acc[t][u][3];
            *(float2*)&out[base2] = ov2;
        }
    }
}

// ---------------------------------------------------------------------------
extern "C" void kernel_launch(void* const* d_in, const int* in_sizes, int n_in,
                              void* d_out, int out_size) {
    const float* h   = (const float*)d_in[0];
    const int*   adj = (const int*)d_in[1];
    const float* W   = (const float*)d_in[2];
    const float* a   = (const float*)d_in[3];
    float* out  = (float*)d_out;
    float* attn = out + (size_t)Bq * Nq * Dq;   // output layout: [out | attention]

    cudaFuncSetAttribute(k_fused, cudaFuncAttributeMaxDynamicSharedMemorySize, SM_TOT);

    k_wa   <<<1, 128>>>(W, a);
    k_wh12 <<<(Bq * Nq) / 8, 256>>>(h);
    k_wh   <<<(Bq * Nq) / TM2, 256>>>(h, W);
    k_fused<<<Bq * (Nq / ROWS_F), 256, SM_TOT>>>(adj, h, out, attn);
}

// round 10
// speedup vs baseline: 1.0003x; 1.0003x over previous
#include <cuda_runtime.h>
#include <cuda_bf16.h>
#include <cstdint>
#include <math_constants.h>

#define Bq 8
#define Nq 2048
#define Dq 128
#define ALPHA 0.2f

// ---------------- scratch (device globals; no allocations allowed) ----------
__device__ float g_w1[Dq];
__device__ float g_w2[Dq];
__device__ float g_Wh1[Bq * Nq];
__device__ float g_Wh2[Bq * Nq];
__device__ __nv_bfloat16 g_Whb[(size_t)Bq * Nq * Dq];   // 4 MB bf16 Wh

// ---------------- K0: w1 = W @ a[:d], w2 = W @ a[d:] ------------------------
__global__ void k_wa(const float* __restrict__ W, const float* __restrict__ a) {
    int k = threadIdx.x;                 // 128 threads
    float s1 = 0.f, s2 = 0.f;
    #pragma unroll 8
    for (int j = 0; j < Dq; j++) {
        float w = W[k * Dq + j];
        s1 += w * a[j];
        s2 += w * a[Dq + j];
    }
    g_w1[k] = s1;
    g_w2[k] = s2;
}

// ---------------- K1: Wh1[row] = h[row]·w1, Wh2[row] = h[row]·w2 ------------
__global__ void __launch_bounds__(256) k_wh12(const float* __restrict__ h) {
    int row  = blockIdx.x * 8 + (threadIdx.x >> 5);
    int lane = threadIdx.x & 31;
    float4 v  = *(const float4*)&h[(size_t)row * Dq + lane * 4];
    float4 u1 = *(const float4*)&g_w1[lane * 4];
    float4 u2 = *(const float4*)&g_w2[lane * 4];
    float s1 = v.x * u1.x + v.y * u1.y + v.z * u1.z + v.w * u1.w;
    float s2 = v.x * u2.x + v.y * u2.y + v.z * u2.z + v.w * u2.w;
    #pragma unroll
    for (int o = 16; o; o >>= 1) {
        s1 += __shfl_xor_sync(0xffffffffu, s1, o);
        s2 += __shfl_xor_sync(0xffffffffu, s2, o);
    }
    if (lane == 0) { g_Wh1[row] = s1; g_Wh2[row] = s2; }
}

// ---------------- K2: Wh = h @ W (fp32 compute) -> bf16 scratch -------------
#define TM2 128
__global__ void __launch_bounds__(256) k_wh(const float* __restrict__ h,
                                            const float* __restrict__ W) {
    __shared__ float As[32][TM2 + 4];   // [k][m] transposed h chunk
    __shared__ float Bs[32][Dq + 4];    // [k][c] W chunk
    const int m0  = blockIdx.x * TM2;
    const int tid = threadIdx.x;
    const int tx  = tid & 15, ty = tid >> 4;

    float acc[8][8];
    #pragma unroll
    for (int i = 0; i < 8; i++)
        #pragma unroll
        for (int j = 0; j < 8; j++) acc[i][j] = 0.f;

    for (int kc = 0; kc < Dq; kc += 32) {
        for (int i = tid; i < 128 * 8; i += 256) {
            int m = i >> 3, f = i & 7;
            float4 v = *(const float4*)&h[(size_t)(m0 + m) * Dq + kc + f * 4];
            As[f * 4 + 0][m] = v.x;
            As[f * 4 + 1][m] = v.y;
            As[f * 4 + 2][m] = v.z;
            As[f * 4 + 3][m] = v.w;
        }
        for (int i = tid; i < 32 * 32; i += 256) {
            int k = i >> 5, f = i & 31;
            *(float4*)&Bs[k][f * 4] = *(const float4*)&W[(size_t)(kc + k) * Dq + f * 4];
        }
        __syncthreads();
        #pragma unroll 8
        for (int k = 0; k < 32; k++) {
            float a8[8], b8[8];
            *(float4*)&a8[0] = *(const float4*)&As[k][ty * 8];
            *(float4*)&a8[4] = *(const float4*)&As[k][ty * 8 + 4];
            *(float4*)&b8[0] = *(const float4*)&Bs[k][tx * 8];
            *(float4*)&b8[4] = *(const float4*)&Bs[k][tx * 8 + 4];
            #pragma unroll
            for (int i = 0; i < 8; i++)
                #pragma unroll
                for (int j = 0; j < 8; j++)
                    acc[i][j] += a8[i] * b8[j];
        }
        __syncthreads();
    }
    #pragma unroll
    for (int i = 0; i < 8; i++) {
        int row = m0 + ty * 8 + i;
        __nv_bfloat162* dst = (__nv_bfloat162*)(g_Whb + (size_t)row * Dq + tx * 8);
        #pragma unroll
        for (int j = 0; j < 4; j++) {
            __nv_bfloat162 t;
            t.x = __float2bfloat16_rn(acc[i][2 * j]);
            t.y = __float2bfloat16_rn(acc[i][2 * j + 1]);
            dst[j] = t;
        }
    }
}

// ---------------- K3 (fused): softmax + attention write + attn @ Wh ---------
// One block = 64 rows of one batch. 256 threads (8 warps).
// Pass A: stream adj once, pack mask bits to smem, online softmax (m, s).
// Pass C: per 128-col K-tile: recompute p, write attention (fp32 out),
//         stage p as bf16 + Wh tile to smem, mma.sync accumulate.
__device__ __forceinline__ void ldmA4(uint32_t* a, uint32_t addr) {
    asm volatile("ldmatrix.sync.aligned.m8n8.x4.shared.b16 {%0,%1,%2,%3}, [%4];"
                 : "=r"(a[0]), "=r"(a[1]), "=r"(a[2]), "=r"(a[3]) : "r"(addr));
}
__device__ __forceinline__ void ldmBt2(uint32_t* b, uint32_t addr) {
    asm volatile("ldmatrix.sync.aligned.m8n8.x2.trans.shared.b16 {%0,%1}, [%2];"
                 : "=r"(b[0]), "=r"(b[1]) : "r"(addr));
}
__device__ __forceinline__ void mma16816(float* c, const uint32_t* a, const uint32_t* b) {
    asm volatile("mma.sync.aligned.m16n8k16.row.col.f32.bf16.bf16.f32 "
                 "{%0,%1,%2,%3}, {%4,%5,%6,%7}, {%8,%9}, {%0,%1,%2,%3};"
                 : "+f"(c[0]), "+f"(c[1]), "+f"(c[2]), "+f"(c[3])
                 : "r"(a[0]), "r"(a[1]), "r"(a[2]), "r"(a[3]), "r"(b[0]), "r"(b[1]));
}

#define ROWS_F 64
#define KTILE 128
#define STR 136                       // bf16 row stride (pad 8)
#define SM_WH2  0                     // 2048 f32          = 8192 B
#define SM_MSK  8192                  // 64*64 u32         = 16384 B
#define SM_AS   24576                 // 64*136 bf16       = 17408 B
#define SM_BS   41984                 // 128*136 bf16      = 34816 B
#define SM_TOT  76800

__global__ void __launch_bounds__(256, 2) k_fused(const int* __restrict__ adj,
                                                  const float* __restrict__ h,
                                                  float* __restrict__ out,
                                                  float* __restrict__ attn) {
    extern __shared__ char sm[];
    float*         wh2s = (float*)(sm + SM_WH2);
    uint32_t*      msk  = (uint32_t*)(sm + SM_MSK);
    __nv_bfloat16* As   = (__nv_bfloat16*)(sm + SM_AS);
    __nv_bfloat16* Bs   = (__nv_bfloat16*)(sm + SM_BS);

    const int tid  = threadIdx.x;
    const int lane = tid & 31;
    const int wid  = tid >> 5;
    const int wy   = wid >> 2;            // 0..1  (32-row strip)
    const int wx   = wid & 3;             // 0..3  (32-col strip)
    const int b    = blockIdx.x >> 5;     // batch
    const int rb0  = (blockIdx.x & 31) * ROWS_F;

    // ---- stage Wh2 (2048 floats) ----
    {
        const float* wh2g = g_Wh2 + (size_t)b * Nq;
        int i = tid * 8;
        *(float4*)&wh2s[i]     = *(const float4*)&wh2g[i];
        *(float4*)&wh2s[i + 4] = *(const float4*)&wh2g[i + 4];
    }
    __syncthreads();

    // ---- pass A: adj stream -> mask bits + online softmax (m, s) ----
    const int r  = tid >> 2;              // 0..63 row within tile
    const int q  = tid & 3;               // quad: col chunk of 512
    const int gr = b * Nq + rb0 + r;      // global row
    const int*   arow = adj + (size_t)gr * Nq;
    const float  wh1r = g_Wh1[gr];

    float m = -CUDART_INF_F, s = 0.f;
    const int c0 = q * 512;
    #pragma unroll 1
    for (int cw = 0; cw < 16; cw++) {
        uint32_t wbits = 0;
        const int cbase = c0 + cw * 32;
        #pragma unroll
        for (int jj = 0; jj < 32; jj += 4) {
            int4   av = *(const int4*)&arow[cbase + jj];
            float4 v  = *(const float4*)&wh2s[cbase + jj];
            float xs[4] = {v.x, v.y, v.z, v.w};
            int   aa[4] = {av.x, av.y, av.z, av.w};
            #pragma unroll
            for (int u = 0; u < 4; u++) {
                float x = wh1r + xs[u];
                float e = x > 0.f ? x : ALPHA * x;
                if (aa[u] > 0) {
                    wbits |= 1u << (jj + u);
                    if (e <= m) s += __expf(e - m);
                    else { s = s * __expf(m - e) + 1.f; m = e; }
                }
            }
        }
        msk[r * 64 + (cbase >> 5)] = wbits;
    }
    // combine the 4 quad-threads of this row (same warp)
    #pragma unroll
    for (int off = 1; off < 4; off <<= 1) {
        float mo = __shfl_xor_sync(0xffffffffu, m, off);
        float so = __shfl_xor_sync(0xffffffffu, s, off);
        float mn = fmaxf(m, mo);
        s = s * __expf(m - mn) + so * __expf(mo - mn);
        m = mn;
    }
    const float inv = 1.0f / s;
    __syncthreads();

    // ---- pass C: K-tiles of 128 cols ----
    float acc[2][4][4];
    #pragma unroll
    for (int t = 0; t < 2; t++)
        #pragma unroll
        for (int u = 0; u < 4; u++)
            #pragma unroll
            for (int p2 = 0; p2 < 4; p2++) acc[t][u][p2] = 0.f;

    const uint32_t as0 = (uint32_t)__cvta_generic_to_shared(As);
    const uint32_t bs0 = (uint32_t)__cvta_generic_to_shared(Bs);
    const int cp = q * 32;                                 // tile-local col base
    const __nv_bfloat16* whb = g_Whb + (size_t)b * Nq * Dq;
    float* arow_out = attn + (size_t)gr * Nq;

    const int brF = tid >> 1;            // B-stage: row 0..127
    const int bcF = (tid & 1) * 64;      // col 0 / 64

    #pragma unroll 1
    for (int kt = 0; kt < Nq / KTILE; kt++) {
        const int ck = kt * KTILE;
        // p subtile: compute, write attention, stage bf16 to As
        {
            const uint32_t wbits = msk[r * 64 + ((ck + cp) >> 5)];
            #pragma unroll
            for (int j = 0; j < 32; j += 4) {
                float4 v = *(const float4*)&wh2s[ck + cp + j];
                float pv[4];
                float xs[4] = {v.x, v.y, v.z, v.w};
                #pragma unroll
                for (int u = 0; u < 4; u++) {
                    float x = wh1r + xs[u];
                    float e = x > 0.f ? x : ALPHA * x;
                    pv[u] = ((wbits >> (j + u)) & 1u) ? __expf(e - m) * inv : 0.f;
                }
                *(float4*)&arow_out[ck + cp + j] = *(float4*)pv;
                __nv_bfloat162 lo, hi;
                lo.x = __float2bfloat16_rn(pv[0]); lo.y = __float2bfloat16_rn(pv[1]);
                hi.x = __float2bfloat16_rn(pv[2]); hi.y = __float2bfloat16_rn(pv[3]);
                uint2 pk;
                pk.x = *(uint32_t*)&lo; pk.y = *(uint32_t*)&hi;
                *(uint2*)&As[r * STR + cp + j] = pk;
            }
        }
        // stage Wh tile 128x128 bf16
        {
            const __nv_bfloat16* wb = whb + (size_t)(ck + brF) * Dq + bcF;
            #pragma unroll
            for (int ii = 0; ii < 8; ii++) {
                uint4 tv = *(const uint4*)(wb + ii * 8);
                *(uint4*)&Bs[brF * STR + bcF + ii * 8] = tv;
            }
        }
        __syncthreads();
        // mma: 8 k-steps of 16
        #pragma unroll
        for (int kk = 0; kk < KTILE; kk += 16) {
            uint32_t afr[2][4];
            #pragma unroll
            for (int t = 0; t < 2; t++) {
                int mr = wy * 32 + t * 16 + (lane & 15);
                uint32_t addr = as0 + ((uint32_t)mr * STR + kk + ((lane >> 4) << 3)) * 2u;
                ldmA4(afr[t], addr);
            }
            uint32_t bfr[4][2];
            #pragma unroll
            for (int u = 0; u < 4; u++) {
                int k = kk + (lane & 15);
                int n = wx * 32 + u * 8;
                uint32_t addr = bs0 + ((uint32_t)k * STR + n) * 2u;
                ldmBt2(bfr[u], addr);
            }
            #pragma unroll
            for (int t = 0; t < 2; t++)
                #pragma unroll
                for (int u = 0; u < 4; u++)
                    mma16816(acc[t][u], afr[t], bfr[u]);
        }
        __syncthreads();
    }

    // ---- epilogue: out = h + acc ----
    #pragma unroll
    for (int t = 0; t < 2; t++) {
        #pragma unroll
        for (int u = 0; u < 4; u++) {
            int rr = rb0 + wy * 32 + t * 16 + (lane >> 2);
            int cc = wx * 32 + u * 8 + (lane & 3) * 2;
            size_t base = ((size_t)b * Nq + rr) * Dq + cc;
            float2 hv = *(const float2*)&h[base];
            float2 ov;
            ov.x = hv.x + acc[t][u][0];
            ov.y = hv.y + acc[t][u][1];
            *(float2*)&out[base] = ov;
            size_t base2 = base + (size_t)8 * Dq;
            float2 hv2 = *(const float2*)&h[base2];
            float2 ov2;
            ov2.x = hv2.x + acc[t][u][2];
            ov2.y = hv2.y + acc[t][u][3];
            *(float2*)&out[base2] = ov2;
        }
    }
}

// ---------------------------------------------------------------------------
extern "C" void kernel_launch(void* const* d_in, const int* in_sizes, int n_in,
                              void* d_out, int out_size) {
    const float* h   = (const float*)d_in[0];
    const int*   adj = (const int*)d_in[1];
    const float* W   = (const float*)d_in[2];
    const float* a   = (const float*)d_in[3];
    float* out  = (float*)d_out;
    float* attn = out + (size_t)Bq * Nq * Dq;   // output layout: [out | attention]

    cudaFuncSetAttribute(k_fused, cudaFuncAttributeMaxDynamicSharedMemorySize, SM_TOT);

    k_wa   <<<1, 128>>>(W, a);
    k_wh12 <<<(Bq * Nq) / 8, 256>>>(h);
    k_wh   <<<(Bq * Nq) / TM2, 256>>>(h, W);
    k_fused<<<Bq * (Nq / ROWS_F), 256, SM_TOT>>>(adj, h, out, attn);
}